// round 1
// baseline (speedup 1.0000x reference)
#include <cuda_runtime.h>
#include <cuda_bf16.h>
#include <math.h>

// Problem constants
#define BB 4
#define FF 16
#define NP 196
#define DIMM 512
#define HH 8
#define DHH 64
#define N_TOT 3137           // 1 + FF*NP
#define BN_TOT (BB * N_TOT)  // 12548
#define QKV_W (3 * HH * DHH) // 1536

// Scratch (device globals — no allocations allowed)
__device__ float g_qkv[(size_t)BN_TOT * QKV_W];   // ~77 MB
__device__ float g_attn[(size_t)BN_TOT * DIMM];   // ~26 MB

// ---------------------------------------------------------------------------
// Tiled SGEMM: C[M,N] = A[M,K] @ B[K,N] (+ bias[N] optional), row-major.
// BM=BN=64, BK=16, 256 threads, 4x4 register microtile per thread.
// ---------------------------------------------------------------------------
#define BM 64
#define BN 64
#define BK 16
#define TM 4
#define TN 4

__global__ __launch_bounds__(256) void sgemm_bias(
    const float* __restrict__ A, const float* __restrict__ B,
    float* __restrict__ C, const float* __restrict__ bias,
    int M, int Nn, int K)
{
    __shared__ float As[BK][BM + 4];
    __shared__ float Bs[BK][BN + 4];

    const int tid  = threadIdx.x;
    const int row0 = blockIdx.y * BM;
    const int col0 = blockIdx.x * BN;
    const int tr = (tid / 16) * TM;
    const int tc = (tid % 16) * TN;

    float acc[TM][TN];
#pragma unroll
    for (int i = 0; i < TM; i++)
#pragma unroll
        for (int j = 0; j < TN; j++) acc[i][j] = 0.f;

    for (int k0 = 0; k0 < K; k0 += BK) {
        // Load A tile (64x16)
#pragma unroll
        for (int i = 0; i < (BM * BK) / 256; i++) {
            int idx = tid + i * 256;
            int r = idx >> 4, c = idx & 15;
            int gr = row0 + r;
            float v = 0.f;
            if (gr < M) v = A[(size_t)gr * K + k0 + c];
            As[c][r] = v;
        }
        // Load B tile (16x64)
#pragma unroll
        for (int i = 0; i < (BK * BN) / 256; i++) {
            int idx = tid + i * 256;
            int c = idx >> 6, n = idx & 63;
            Bs[c][n] = B[(size_t)(k0 + c) * Nn + col0 + n];
        }
        __syncthreads();

#pragma unroll
        for (int k = 0; k < BK; k++) {
            float a[TM], bb[TN];
#pragma unroll
            for (int i = 0; i < TM; i++) a[i] = As[k][tr + i];
#pragma unroll
            for (int j = 0; j < TN; j++) bb[j] = Bs[k][tc + j];
#pragma unroll
            for (int i = 0; i < TM; i++)
#pragma unroll
                for (int j = 0; j < TN; j++) acc[i][j] += a[i] * bb[j];
        }
        __syncthreads();
    }

#pragma unroll
    for (int i = 0; i < TM; i++) {
        int gr = row0 + tr + i;
        if (gr >= M) continue;
#pragma unroll
        for (int j = 0; j < TN; j++) {
            int gc = col0 + tc + j;
            float v = acc[i][j];
            if (bias) v += bias[gc];
            C[(size_t)gr * Nn + gc] = v;
        }
    }
}

// ---------------------------------------------------------------------------
// Frame-local attention: one CTA per (b, h, f).
// K/V (197 x 64) resident in dynamic smem; queries tiled by 8.
// Key j=0 is the CLS key/value of the same (b,h); j=1..196 are frame tokens.
// ---------------------------------------------------------------------------
#define KP 65   // padded K/V row stride (bank-conflict free)
#define SP 200  // padded sim row stride
#define QT 8    // query tile

__global__ __launch_bounds__(256) void frame_attn_kernel(
    const float* __restrict__ qkv, float* __restrict__ attn_out)
{
    extern __shared__ float sm[];
    float* Ks = sm;                 // 197*65
    float* Vs = Ks + 197 * KP;      // 197*65
    float* qs = Vs + 197 * KP;      // 8*65
    float* sr = qs + QT * KP;       // 8*200

    const int tid = threadIdx.x;
    const int bhf = blockIdx.x;
    const int fi = bhf % FF;
    const int bh = bhf / FF;
    const int h = bh % HH;
    const int b = bh / HH;

    const size_t base = (size_t)b * N_TOT * QKV_W;
    const int qoff = h * DHH;
    const int koff = DIMM + h * DHH;
    const int voff = 2 * DIMM + h * DHH;

    // Load K and V tiles into smem
    for (int idx = tid; idx < 197 * 64; idx += 256) {
        int j = idx >> 6, d = idx & 63;
        int n = (j == 0) ? 0 : (1 + fi * NP + (j - 1));
        const float* src = qkv + base + (size_t)n * QKV_W;
        Ks[j * KP + d] = src[koff + d];
        Vs[j * KP + d] = src[voff + d];
    }
    __syncthreads();

    const float scale = 0.125f; // 1/sqrt(64)

    for (int qt = 0; qt < NP; qt += QT) {
        const int qcnt = min(QT, NP - qt);

        // Load (and scale) query tile
        for (int idx = tid; idx < qcnt * 64; idx += 256) {
            int qi = idx >> 6, d = idx & 63;
            int n = 1 + fi * NP + qt + qi;
            qs[qi * KP + d] = qkv[base + (size_t)n * QKV_W + qoff + d] * scale;
        }
        __syncthreads();

        // sim[qi][j] = q . k
        for (int idx = tid; idx < qcnt * 197; idx += 256) {
            int qi = idx / 197, j = idx - qi * 197;
            const float* qp = qs + qi * KP;
            const float* kp = Ks + j * KP;
            float dot = 0.f;
#pragma unroll
            for (int d = 0; d < 64; d++) dot += qp[d] * kp[d];
            sr[qi * SP + j] = dot;
        }
        __syncthreads();

        // softmax: warp w handles row w
        {
            int w = tid >> 5, lane = tid & 31;
            if (w < qcnt) {
                float* row = sr + w * SP;
                float m = -1e30f;
                for (int j = lane; j < 197; j += 32) m = fmaxf(m, row[j]);
#pragma unroll
                for (int o = 16; o > 0; o >>= 1)
                    m = fmaxf(m, __shfl_xor_sync(0xffffffffu, m, o));
                float s = 0.f;
                for (int j = lane; j < 197; j += 32) {
                    float e = __expf(row[j] - m);
                    row[j] = e;
                    s += e;
                }
#pragma unroll
                for (int o = 16; o > 0; o >>= 1)
                    s += __shfl_xor_sync(0xffffffffu, s, o);
                float inv = 1.f / s;
                for (int j = lane; j < 197; j += 32) row[j] *= inv;
            }
        }
        __syncthreads();

        // out[qi][d] = sum_j p[qi][j] * V[j][d]
        for (int idx = tid; idx < qcnt * 64; idx += 256) {
            int qi = idx >> 6, d = idx & 63;
            const float* row = sr + qi * SP;
            float a = 0.f;
            for (int j = 0; j < 197; j++) a += row[j] * Vs[j * KP + d];
            int n = 1 + fi * NP + qt + qi;
            attn_out[((size_t)(b * N_TOT + n)) * DIMM + h * DHH + d] = a;
        }
        __syncthreads();
    }
}

// ---------------------------------------------------------------------------
// CLS attention: one CTA per (b, h). CLS query attends over all 3137 keys.
// ---------------------------------------------------------------------------
__global__ __launch_bounds__(256) void cls_attn_kernel(
    const float* __restrict__ qkv, float* __restrict__ attn_out)
{
    __shared__ float q0[64];
    __shared__ float sim[N_TOT];
    __shared__ float red[256];
    __shared__ float acc4[4 * 64];

    const int tid = threadIdx.x;
    const int bh = blockIdx.x;
    const int h = bh % HH;
    const int b = bh / HH;
    const size_t base = (size_t)b * N_TOT * QKV_W;

    if (tid < 64) q0[tid] = qkv[base + h * DHH + tid] * 0.125f;
    __syncthreads();

    // logits
    for (int n = tid; n < N_TOT; n += 256) {
        const float* kp = qkv + base + (size_t)n * QKV_W + DIMM + h * DHH;
        float dot = 0.f;
#pragma unroll
        for (int d = 0; d < 64; d++) dot += q0[d] * kp[d];
        sim[n] = dot;
    }
    __syncthreads();

    // block max
    float m = -1e30f;
    for (int n = tid; n < N_TOT; n += 256) m = fmaxf(m, sim[n]);
    red[tid] = m;
    __syncthreads();
    for (int s = 128; s > 0; s >>= 1) {
        if (tid < s) red[tid] = fmaxf(red[tid], red[tid + s]);
        __syncthreads();
    }
    m = red[0];
    __syncthreads();

    // exp + sum
    float ssum = 0.f;
    for (int n = tid; n < N_TOT; n += 256) {
        float e = __expf(sim[n] - m);
        sim[n] = e;
        ssum += e;
    }
    red[tid] = ssum;
    __syncthreads();
    for (int s = 128; s > 0; s >>= 1) {
        if (tid < s) red[tid] += red[tid + s];
        __syncthreads();
    }
    const float inv = 1.f / red[0];
    __syncthreads();

    // weighted sum over V: thread (nn, d), nn = tid/64 in 0..3
    const int nn = tid >> 6;
    const int d = tid & 63;
    float a = 0.f;
    for (int n = nn; n < N_TOT; n += 4)
        a += sim[n] * qkv[base + (size_t)n * QKV_W + 2 * DIMM + h * DHH + d];
    acc4[tid] = a;
    __syncthreads();

    if (tid < 64) {
        float v = (acc4[tid] + acc4[tid + 64] + acc4[tid + 128] + acc4[tid + 192]) * inv;
        attn_out[((size_t)b * N_TOT) * DIMM + h * DHH + tid] = v;
    }
}

// ---------------------------------------------------------------------------
// Launch
// ---------------------------------------------------------------------------
extern "C" void kernel_launch(void* const* d_in, const int* in_sizes, int n_in,
                              void* d_out, int out_size)
{
    const float* x     = (const float*)d_in[0]; // (B, N, 512)
    const float* W_qkv = (const float*)d_in[1]; // (512, 1536)
    const float* W_out = (const float*)d_in[2]; // (512, 512)
    const float* b_out = (const float*)d_in[3]; // (512,)
    float* out = (float*)d_out;                 // (B, N, 512)

    void* pq = nullptr; void* pa = nullptr;
    cudaGetSymbolAddress(&pq, g_qkv);
    cudaGetSymbolAddress(&pa, g_attn);
    float* qkv = (float*)pq;
    float* attn = (float*)pa;

    // 1) QKV GEMM: (12548 x 512) @ (512 x 1536)
    {
        dim3 grid(QKV_W / BN, (BN_TOT + BM - 1) / BM);
        sgemm_bias<<<grid, 256>>>(x, W_qkv, qkv, nullptr, BN_TOT, QKV_W, DIMM);
    }

    // 2) Attention
    {
        const int smem_bytes = (2 * 197 * KP + QT * KP + QT * SP) * (int)sizeof(float);
        cudaFuncSetAttribute(frame_attn_kernel,
                             cudaFuncAttributeMaxDynamicSharedMemorySize, smem_bytes);
        frame_attn_kernel<<<BB * HH * FF, 256, smem_bytes>>>(qkv, attn);
        cls_attn_kernel<<<BB * HH, 256>>>(qkv, attn);
    }

    // 3) Output GEMM + bias: (12548 x 512) @ (512 x 512) + b
    {
        dim3 grid(DIMM / BN, (BN_TOT + BM - 1) / BM);
        sgemm_bias<<<grid, 256>>>(attn, W_out, out, b_out, BN_TOT, DIMM, DIMM);
    }
}

// round 6
// speedup vs baseline: 1.8982x; 1.8982x over previous
#include <cuda_runtime.h>
#include <cuda_bf16.h>
#include <cstdint>
#include <math.h>

// ---------------------------------------------------------------------------
// Problem constants
// ---------------------------------------------------------------------------
#define BB 4
#define FF 16
#define NP 196
#define DIMM 512
#define HH 8
#define DHH 64
#define N_TOT 3137           // 1 + FF*NP
#define BN_TOT (BB * N_TOT)  // 12548
#define QKV_W (3 * HH * DHH) // 1536

// Scratch (device globals — no allocations allowed)
__device__ float g_qkv[(size_t)BN_TOT * QKV_W];   // ~77 MB
__device__ float g_attn[(size_t)BN_TOT * DIMM];   // ~26 MB
__device__ float g_xr[(size_t)BN_TOT * DIMM];     // tf32-rounded x (~26 MB)
__device__ float g_wt[(size_t)QKV_W * DIMM + (size_t)DIMM * DIMM]; // transposed weights

// ---------------------------------------------------------------------------
// Helpers
// ---------------------------------------------------------------------------
__device__ __forceinline__ uint32_t smem_u32(const void* p) {
    uint32_t a;
    asm("{ .reg .u64 t; cvta.to.shared.u64 t, %1; cvt.u32.u64 %0, t; }" : "=r"(a) : "l"(p));
    return a;
}

__device__ __forceinline__ float tf32r(float f) {
    uint32_t u;
    asm("cvt.rna.tf32.f32 %0, %1;" : "=r"(u) : "f"(f));
    return __uint_as_float(u);
}

#define LDSM_X4(r, addr) \
    asm volatile("ldmatrix.sync.aligned.m8n8.x4.shared.b16 {%0,%1,%2,%3}, [%4];" \
        : "=r"((r)[0]), "=r"((r)[1]), "=r"((r)[2]), "=r"((r)[3]) : "r"(addr))

#define MMA_TF32(c, a, b0v, b1v) \
    asm volatile("mma.sync.aligned.m16n8k8.row.col.f32.tf32.tf32.f32 " \
        "{%0,%1,%2,%3}, {%4,%5,%6,%7}, {%8,%9}, {%0,%1,%2,%3};" \
        : "+f"((c)[0]), "+f"((c)[1]), "+f"((c)[2]), "+f"((c)[3]) \
        : "r"((a)[0]), "r"((a)[1]), "r"((a)[2]), "r"((a)[3]), "r"(b0v), "r"(b1v))

#define CP_ASYNC16(saddr, gptr, szr) \
    asm volatile("cp.async.cg.shared.global [%0], [%1], 16, %2;" \
        :: "r"(saddr), "l"(gptr), "r"(szr))
#define CP_COMMIT() asm volatile("cp.async.commit_group;")
#define CP_WAIT0()  asm volatile("cp.async.wait_group 0;")

// ---------------------------------------------------------------------------
// Round x to tf32 (rna) — prepares the A operand of GEMM1.
// ---------------------------------------------------------------------------
__global__ __launch_bounds__(256) void round_tf32_kernel(
    const float* __restrict__ in, float* __restrict__ out, int n4)
{
    int i = blockIdx.x * 256 + threadIdx.x;
    if (i < n4) {
        float4 v = ((const float4*)in)[i];
        v.x = tf32r(v.x); v.y = tf32r(v.y); v.z = tf32r(v.z); v.w = tf32r(v.w);
        ((float4*)out)[i] = v;
    }
}

// ---------------------------------------------------------------------------
// Weight transpose + tf32 round: W[K=512][N] -> WT[N][512]
// ---------------------------------------------------------------------------
__global__ __launch_bounds__(256) void transpose512(const float* __restrict__ W,
                                                    float* __restrict__ WT, int N) {
    __shared__ float t[32][33];
    const int tx = threadIdx.x & 31, ty = threadIdx.x >> 5; // 32x8
    const int bn = blockIdx.x * 32, bk = blockIdx.y * 32;
#pragma unroll
    for (int i = 0; i < 32; i += 8)
        t[ty + i][tx] = W[(size_t)(bk + ty + i) * N + bn + tx];
    __syncthreads();
#pragma unroll
    for (int i = 0; i < 32; i += 8)
        WT[(size_t)(bn + ty + i) * 512 + bk + tx] = tf32r(t[tx][ty + i]);
}

// ---------------------------------------------------------------------------
// tf32 mma.sync GEMM: C[M,N] = A[M,512] @ BT[N,512]^T (+bias)
// CTA 128x128, BK=32, 256 threads (8 warps, 2x4), warp tile 64x32.
// cp.async 2-stage double buffer. Inputs must be pre-rounded to tf32.
// ---------------------------------------------------------------------------
#define AS_STRIDE 36                     // floats per smem row (padding: +4 banks/row)
#define TILE_F (128 * AS_STRIDE)         // floats per tile
#define TILE_B (TILE_F * 4)              // 18432 bytes
#define G_SMEM_BYTES (4 * TILE_B)        // A0 A1 B0 B1 = 73728

__global__ __launch_bounds__(256) void gemm_tf32_mma(
    const float* __restrict__ A, const float* __restrict__ BT,
    float* __restrict__ C, const float* __restrict__ bias, int M, int Nn)
{
    extern __shared__ float smf[];
    const uint32_t sb = smem_u32(smf);
    const int tid = threadIdx.x;
    const int lane = tid & 31;
    const int wid = tid >> 5;
    const int warpM = wid & 1;   // 0..1 (64-row halves)
    const int warpN = wid >> 1;  // 0..3 (32-col quarters)
    const int m0 = blockIdx.y * 128;
    const int n0 = blockIdx.x * 128;

    // staging thread mapping: id -> (row, kg) with row = id>>3, kg = id&7 (float4s)
    const int s_row = tid >> 3;         // rows s_row, s_row+32, +64, +96
    const int s_kg = tid & 7;

    float acc[4][4][4];
#pragma unroll
    for (int mt = 0; mt < 4; mt++)
#pragma unroll
        for (int nt = 0; nt < 4; nt++)
#pragma unroll
            for (int r = 0; r < 4; r++) acc[mt][nt][r] = 0.f;

    // ldsm lane addressing (bytes, relative to tile base)
    const int aRow = warpM * 64 + (lane & 7) + ((lane >> 3) & 1) * 8;
    const uint32_t aLane = (uint32_t)(aRow * AS_STRIDE + (lane >> 4) * 4) * 4;
    const int bRow = warpN * 32 + ((lane >> 4) & 1) * 8 + (lane & 7);
    const uint32_t bLane = (uint32_t)(bRow * AS_STRIDE + ((lane >> 3) & 1) * 4) * 4;

    // stage chunk 0 into buffer 0
    {
#pragma unroll
        for (int i = 0; i < 4; i++) {
            int row = s_row + i * 32;
            uint32_t sa = sb + (uint32_t)(row * AS_STRIDE + s_kg * 4) * 4;
            int szA = (m0 + row < M) ? 16 : 0;
            CP_ASYNC16(sa, &A[(size_t)(m0 + row) * 512 + s_kg * 4], szA);
            uint32_t sbp = sb + 2u * TILE_B + (uint32_t)(row * AS_STRIDE + s_kg * 4) * 4;
            CP_ASYNC16(sbp, &BT[(size_t)(n0 + row) * 512 + s_kg * 4], 16);
        }
        CP_COMMIT();
    }

    for (int c = 0; c < 16; c++) {
        const int b = c & 1;
        CP_WAIT0();
        __syncthreads();

        if (c + 1 < 16) {
            const int nb = b ^ 1;
            const int k0 = (c + 1) * 32;
#pragma unroll
            for (int i = 0; i < 4; i++) {
                int row = s_row + i * 32;
                uint32_t sa = sb + (uint32_t)nb * TILE_B +
                              (uint32_t)(row * AS_STRIDE + s_kg * 4) * 4;
                int szA = (m0 + row < M) ? 16 : 0;
                CP_ASYNC16(sa, &A[(size_t)(m0 + row) * 512 + k0 + s_kg * 4], szA);
                uint32_t sbp = sb + (uint32_t)(2 + nb) * TILE_B +
                               (uint32_t)(row * AS_STRIDE + s_kg * 4) * 4;
                CP_ASYNC16(sbp, &BT[(size_t)(n0 + row) * 512 + k0 + s_kg * 4], 16);
            }
            CP_COMMIT();
        }

        // compute chunk c from buffer b
        const uint32_t aBuf = sb + (uint32_t)b * TILE_B;
        const uint32_t bBuf = sb + (uint32_t)(2 + b) * TILE_B;
#pragma unroll
        for (int s = 0; s < 4; s++) {
            uint32_t af[4][4];
#pragma unroll
            for (int mt = 0; mt < 4; mt++)
                LDSM_X4(af[mt], aBuf + aLane + (uint32_t)(mt * 16 * AS_STRIDE * 4 + s * 32));
            uint32_t bf[2][4];
#pragma unroll
            for (int p = 0; p < 2; p++)
                LDSM_X4(bf[p], bBuf + bLane + (uint32_t)(p * 16 * AS_STRIDE * 4 + s * 32));
#pragma unroll
            for (int mt = 0; mt < 4; mt++)
#pragma unroll
                for (int nt = 0; nt < 4; nt++)
                    MMA_TF32(acc[mt][nt], af[mt], bf[nt >> 1][(nt & 1) * 2],
                             bf[nt >> 1][(nt & 1) * 2 + 1]);
        }
    }

    // epilogue: direct register -> gmem stores with bias
#pragma unroll
    for (int mt = 0; mt < 4; mt++) {
        const int r0 = m0 + warpM * 64 + mt * 16 + (lane >> 2);
#pragma unroll
        for (int nt = 0; nt < 4; nt++) {
            const int col = n0 + warpN * 32 + nt * 8 + (lane & 3) * 2;
            float bx = 0.f, by = 0.f;
            if (bias) { bx = __ldg(&bias[col]); by = __ldg(&bias[col + 1]); }
            if (r0 < M) {
                float2 v = make_float2(acc[mt][nt][0] + bx, acc[mt][nt][1] + by);
                *(float2*)&C[(size_t)r0 * Nn + col] = v;
            }
            if (r0 + 8 < M) {
                float2 v = make_float2(acc[mt][nt][2] + bx, acc[mt][nt][3] + by);
                *(float2*)&C[(size_t)(r0 + 8) * Nn + col] = v;
            }
        }
    }
}

// ---------------------------------------------------------------------------
// Frame-local attention: one CTA per (b, h, f), 256 threads (8 warps).
// K/V (197 x 64 fp32) in smem; queries in tiles of 16.
// sim:  warp w -> (8-query group g = w&1, j-band (w>>1)*50)
// PV:   warp w -> queries {2w, 2w+1}; lane -> (d-float4, j-half); shfl reduce
// Output stores are tf32-rounded (feeds GEMM2).
// ---------------------------------------------------------------------------
#define KP 68
#define SP 200
#define QT 16
#define FA_SMEM ((2 * 197 * KP + QT * KP + QT * SP) * 4)

__global__ __launch_bounds__(256) void frame_attn_kernel(
    const float* __restrict__ qkv, float* __restrict__ attn_out)
{
    extern __shared__ float sm[];
    float* Ks = sm;                 // 197*KP
    float* Vs = Ks + 197 * KP;      // 197*KP
    float* qs = Vs + 197 * KP;      // QT*KP
    float* sr = qs + QT * KP;       // QT*SP

    const int tid = threadIdx.x;
    const int w = tid >> 5;
    const int l = tid & 31;
    const int bhf = blockIdx.x;
    const int fi = bhf % FF;
    const int bh = bhf / FF;
    const int h = bh % HH;
    const int b = bh / HH;

    const size_t base = (size_t)b * N_TOT * QKV_W;
    const int qoff = h * DHH;
    const int koff = DIMM + h * DHH;
    const int voff = 2 * DIMM + h * DHH;

    // Load K and V tiles (float4); j=0 is the CLS token
    for (int idx = tid; idx < 197 * 16; idx += 256) {
        int j = idx >> 4, dg = idx & 15;
        int n = (j == 0) ? 0 : (1 + fi * NP + (j - 1));
        const float* src = qkv + base + (size_t)n * QKV_W;
        *(float4*)&Ks[j * KP + dg * 4] = *(const float4*)&src[koff + dg * 4];
        *(float4*)&Vs[j * KP + dg * 4] = *(const float4*)&src[voff + dg * 4];
    }
    __syncthreads();

    const float scale = 0.125f;

    // sim-phase mapping: 2 query groups x 4 j-bands of 50
    const int g = w & 1;
    const int jbase = (w >> 1) * 50;
    const int jend = min(197, jbase + 50);
    const bool va = (jbase + l) < jend;
    const bool vb = (jbase + l + 32) < jend;
    const int ja = va ? (jbase + l) : jbase;
    const int jb2 = vb ? (jbase + l + 32) : jbase;

    for (int qt = 0; qt < NP; qt += QT) {
        const int qcnt = min(QT, NP - qt);

        // Load (and scale) query tile; zero-pad rows >= qcnt. 256 f4 = 256 threads.
        {
            int qi = tid >> 4, dg = tid & 15;
            float4 v = make_float4(0.f, 0.f, 0.f, 0.f);
            if (qi < qcnt) {
                int n = 1 + fi * NP + qt + qi;
                v = *(const float4*)&qkv[base + (size_t)n * QKV_W + qoff + dg * 4];
                v.x *= scale; v.y *= scale; v.z *= scale; v.w *= scale;
            }
            *(float4*)&qs[qi * KP + dg * 4] = v;
        }
        __syncthreads();

        // sim[qi][j] = q . k   (8 queries x 2 j per warp, register-tiled)
        {
            float acc[16];
#pragma unroll
            for (int i = 0; i < 16; i++) acc[i] = 0.f;
#pragma unroll 4
            for (int d4 = 0; d4 < 16; d4++) {
                float4 ka = *(const float4*)&Ks[ja * KP + d4 * 4];
                float4 kb = *(const float4*)&Ks[jb2 * KP + d4 * 4];
#pragma unroll
                for (int qq = 0; qq < 8; qq++) {
                    float4 qv = *(const float4*)&qs[(g * 8 + qq) * KP + d4 * 4];
                    acc[qq * 2 + 0] += qv.x * ka.x + qv.y * ka.y + qv.z * ka.z + qv.w * ka.w;
                    acc[qq * 2 + 1] += qv.x * kb.x + qv.y * kb.y + qv.z * kb.z + qv.w * kb.w;
                }
            }
#pragma unroll
            for (int qq = 0; qq < 8; qq++) {
                if (va) sr[(g * 8 + qq) * SP + jbase + l] = acc[qq * 2 + 0];
                if (vb) sr[(g * 8 + qq) * SP + jbase + l + 32] = acc[qq * 2 + 1];
            }
        }
        __syncthreads();

        // softmax: warp w handles rows w and w+8
#pragma unroll
        for (int rr = 0; rr < 2; rr++) {
            int r = w + rr * 8;
            if (r < qcnt) {
                float* row = sr + r * SP;
                float m = -1e30f;
                for (int j = l; j < 197; j += 32) m = fmaxf(m, row[j]);
#pragma unroll
                for (int o = 16; o > 0; o >>= 1)
                    m = fmaxf(m, __shfl_xor_sync(0xffffffffu, m, o));
                float s = 0.f;
                for (int j = l; j < 197; j += 32) {
                    float e = __expf(row[j] - m);
                    row[j] = e;
                    s += e;
                }
#pragma unroll
                for (int o = 16; o > 0; o >>= 1)
                    s += __shfl_xor_sync(0xffffffffu, s, o);
                float inv = 1.f / s;
                for (int j = l; j < 197; j += 32) row[j] *= inv;
            }
        }
        __syncthreads();

        // PV: warp w -> queries 2w, 2w+1. lane: dg = l&15, jh = l>>4.
        {
            const int q0 = 2 * w, q1 = 2 * w + 1;
            const int dg = l & 15;
            const int jh = l >> 4;
            const float* s0 = sr + q0 * SP;
            const float* s1 = sr + q1 * SP;
            float4 a0 = make_float4(0.f, 0.f, 0.f, 0.f);
            float4 a1 = make_float4(0.f, 0.f, 0.f, 0.f);
            for (int jj = 0; jj < 99; jj++) {
                int j = jh * 99 + jj;
                if (j < 197) {
                    float p0 = s0[j], p1 = s1[j];
                    float4 v = *(const float4*)&Vs[j * KP + dg * 4];
                    a0.x += p0 * v.x; a0.y += p0 * v.y; a0.z += p0 * v.z; a0.w += p0 * v.w;
                    a1.x += p1 * v.x; a1.y += p1 * v.y; a1.z += p1 * v.z; a1.w += p1 * v.w;
                }
            }
            a0.x += __shfl_xor_sync(0xffffffffu, a0.x, 16);
            a0.y += __shfl_xor_sync(0xffffffffu, a0.y, 16);
            a0.z += __shfl_xor_sync(0xffffffffu, a0.z, 16);
            a0.w += __shfl_xor_sync(0xffffffffu, a0.w, 16);
            a1.x += __shfl_xor_sync(0xffffffffu, a1.x, 16);
            a1.y += __shfl_xor_sync(0xffffffffu, a1.y, 16);
            a1.z += __shfl_xor_sync(0xffffffffu, a1.z, 16);
            a1.w += __shfl_xor_sync(0xffffffffu, a1.w, 16);
            if (l < 16) {
                if (q0 < qcnt) {
                    int n = 1 + fi * NP + qt + q0;
                    float4 o = make_float4(tf32r(a0.x), tf32r(a0.y), tf32r(a0.z), tf32r(a0.w));
                    *(float4*)&attn_out[((size_t)(b * N_TOT + n)) * DIMM + h * DHH + dg * 4] = o;
                }
                if (q1 < qcnt) {
                    int n = 1 + fi * NP + qt + q1;
                    float4 o = make_float4(tf32r(a1.x), tf32r(a1.y), tf32r(a1.z), tf32r(a1.w));
                    *(float4*)&attn_out[((size_t)(b * N_TOT + n)) * DIMM + h * DHH + dg * 4] = o;
                }
            }
        }
        __syncthreads();
    }
}

// ---------------------------------------------------------------------------
// CLS attention: one CTA per (b, h). CLS query attends over all 3137 keys.
// ---------------------------------------------------------------------------
__global__ __launch_bounds__(256) void cls_attn_kernel(
    const float* __restrict__ qkv, float* __restrict__ attn_out)
{
    __shared__ float q0[64];
    __shared__ float sim[N_TOT];
    __shared__ float red[256];
    __shared__ float acc4[4 * 64];

    const int tid = threadIdx.x;
    const int bh = blockIdx.x;
    const int h = bh % HH;
    const int b = bh / HH;
    const size_t base = (size_t)b * N_TOT * QKV_W;

    if (tid < 64) q0[tid] = qkv[base + h * DHH + tid] * 0.125f;
    __syncthreads();

    for (int n = tid; n < N_TOT; n += 256) {
        const float* kp = qkv + base + (size_t)n * QKV_W + DIMM + h * DHH;
        float dot = 0.f;
#pragma unroll
        for (int d = 0; d < 64; d++) dot += q0[d] * kp[d];
        sim[n] = dot;
    }
    __syncthreads();

    float m = -1e30f;
    for (int n = tid; n < N_TOT; n += 256) m = fmaxf(m, sim[n]);
    red[tid] = m;
    __syncthreads();
    for (int s = 128; s > 0; s >>= 1) {
        if (tid < s) red[tid] = fmaxf(red[tid], red[tid + s]);
        __syncthreads();
    }
    m = red[0];
    __syncthreads();

    float ssum = 0.f;
    for (int n = tid; n < N_TOT; n += 256) {
        float e = __expf(sim[n] - m);
        sim[n] = e;
        ssum += e;
    }
    red[tid] = ssum;
    __syncthreads();
    for (int s = 128; s > 0; s >>= 1) {
        if (tid < s) red[tid] += red[tid + s];
        __syncthreads();
    }
    const float inv = 1.f / red[0];
    __syncthreads();

    const int nn = tid >> 6;
    const int d = tid & 63;
    float a = 0.f;
    for (int n = nn; n < N_TOT; n += 4)
        a += sim[n] * qkv[base + (size_t)n * QKV_W + 2 * DIMM + h * DHH + d];
    acc4[tid] = a;
    __syncthreads();

    if (tid < 64) {
        float v = (acc4[tid] + acc4[tid + 64] + acc4[tid + 128] + acc4[tid + 192]) * inv;
        attn_out[((size_t)b * N_TOT) * DIMM + h * DHH + tid] = tf32r(v);
    }
}

// ---------------------------------------------------------------------------
// Launch
// ---------------------------------------------------------------------------
extern "C" void kernel_launch(void* const* d_in, const int* in_sizes, int n_in,
                              void* d_out, int out_size)
{
    const float* x     = (const float*)d_in[0]; // (B, N, 512)
    const float* W_qkv = (const float*)d_in[1]; // (512, 1536)
    const float* W_out = (const float*)d_in[2]; // (512, 512)
    const float* b_out = (const float*)d_in[3]; // (512,)
    float* out = (float*)d_out;                 // (B, N, 512)

    void *pq = nullptr, *pa = nullptr, *pw = nullptr, *px = nullptr;
    cudaGetSymbolAddress(&pq, g_qkv);
    cudaGetSymbolAddress(&pa, g_attn);
    cudaGetSymbolAddress(&pw, g_wt);
    cudaGetSymbolAddress(&px, g_xr);
    float* qkv  = (float*)pq;
    float* attn = (float*)pa;
    float* xr   = (float*)px;
    float* wt_qkv = (float*)pw;                       // [1536][512]
    float* wt_out = wt_qkv + (size_t)QKV_W * DIMM;    // [512][512]

    cudaFuncSetAttribute(gemm_tf32_mma, cudaFuncAttributeMaxDynamicSharedMemorySize,
                         G_SMEM_BYTES);
    cudaFuncSetAttribute(frame_attn_kernel,
                         cudaFuncAttributeMaxDynamicSharedMemorySize, FA_SMEM);

    // 0) round x to tf32; transpose + round weights
    {
        int n4 = BN_TOT * DIMM / 4;
        round_tf32_kernel<<<(n4 + 255) / 256, 256>>>(x, xr, n4);
        transpose512<<<dim3(QKV_W / 32, DIMM / 32), 256>>>(W_qkv, wt_qkv, QKV_W);
        transpose512<<<dim3(DIMM / 32, DIMM / 32), 256>>>(W_out, wt_out, DIMM);
    }

    // 1) QKV GEMM: (12548 x 512) @ (512 x 1536)
    {
        dim3 grid(QKV_W / 128, (BN_TOT + 127) / 128);
        gemm_tf32_mma<<<grid, 256, G_SMEM_BYTES>>>(xr, wt_qkv, qkv, nullptr, BN_TOT, QKV_W);
    }

    // 2) Attention
    {
        frame_attn_kernel<<<BB * HH * FF, 256, FA_SMEM>>>(qkv, attn);
        cls_attn_kernel<<<BB * HH, 256>>>(qkv, attn);
    }

    // 3) Output GEMM + bias: (12548 x 512) @ (512 x 512) + b
    {
        dim3 grid(DIMM / 128, (BN_TOT + 127) / 128);
        gemm_tf32_mma<<<grid, 256, G_SMEM_BYTES>>>(attn, wt_out, out, b_out, BN_TOT, DIMM);
    }
}

// round 17
// speedup vs baseline: 2.5807x; 1.3595x over previous
#include <cuda_runtime.h>
#include <cuda_bf16.h>
#include <cstdint>
#include <math.h>

// ---------------------------------------------------------------------------
// Problem constants
// ---------------------------------------------------------------------------
#define BB 4
#define FF 16
#define NP 196
#define DIMM 512
#define HH 8
#define DHH 64
#define N_TOT 3137           // 1 + FF*NP
#define BN_TOT (BB * N_TOT)  // 12548
#define QKV_W (3 * HH * DHH) // 1536

// Scratch (device globals — no allocations allowed)
__device__ float g_qkv[(size_t)BN_TOT * QKV_W];
__device__ float g_attn[(size_t)BN_TOT * DIMM];
__device__ float g_xr[(size_t)BN_TOT * DIMM];
__device__ float g_wt[(size_t)QKV_W * DIMM + (size_t)DIMM * DIMM];

// ---------------------------------------------------------------------------
// Helpers
// ---------------------------------------------------------------------------
__device__ __forceinline__ uint32_t smem_u32(const void* p) {
    uint32_t a;
    asm("{ .reg .u64 t; cvta.to.shared.u64 t, %1; cvt.u32.u64 %0, t; }" : "=r"(a) : "l"(p));
    return a;
}

__device__ __forceinline__ float tf32r(float f) {
    uint32_t u;
    asm("cvt.rna.tf32.f32 %0, %1;" : "=r"(u) : "f"(f));
    return __uint_as_float(u);
}

#define LDSM_X4(r, addr) \
    asm volatile("ldmatrix.sync.aligned.m8n8.x4.shared.b16 {%0,%1,%2,%3}, [%4];" \
        : "=r"((r)[0]), "=r"((r)[1]), "=r"((r)[2]), "=r"((r)[3]) : "r"(addr))

#define LDSM_X2(r, addr) \
    asm volatile("ldmatrix.sync.aligned.m8n8.x2.shared.b16 {%0,%1}, [%2];" \
        : "=r"((r)[0]), "=r"((r)[1]) : "r"(addr))

#define MMA_TF32(c, a, b0v, b1v) \
    asm volatile("mma.sync.aligned.m16n8k8.row.col.f32.tf32.tf32.f32 " \
        "{%0,%1,%2,%3}, {%4,%5,%6,%7}, {%8,%9}, {%0,%1,%2,%3};" \
        : "+f"((c)[0]), "+f"((c)[1]), "+f"((c)[2]), "+f"((c)[3]) \
        : "r"((a)[0]), "r"((a)[1]), "r"((a)[2]), "r"((a)[3]), "r"(b0v), "r"(b1v))

#define CP_ASYNC16(saddr, gptr, szr) \
    asm volatile("cp.async.cg.shared.global [%0], [%1], 16, %2;" \
        :: "r"(saddr), "l"(gptr), "r"(szr))
#define CP_COMMIT() asm volatile("cp.async.commit_group;")
#define CP_WAIT0()  asm volatile("cp.async.wait_group 0;")

// ---------------------------------------------------------------------------
// Round x to tf32 (rna)
// ---------------------------------------------------------------------------
__global__ __launch_bounds__(256) void round_tf32_kernel(
    const float* __restrict__ in, float* __restrict__ out, int n4)
{
    int i = blockIdx.x * 256 + threadIdx.x;
    if (i < n4) {
        float4 v = ((const float4*)in)[i];
        v.x = tf32r(v.x); v.y = tf32r(v.y); v.z = tf32r(v.z); v.w = tf32r(v.w);
        ((float4*)out)[i] = v;
    }
}

// ---------------------------------------------------------------------------
// Weight transpose + tf32 round: W[K=512][N] -> WT[N][512]
// ---------------------------------------------------------------------------
__global__ __launch_bounds__(256) void transpose512(const float* __restrict__ W,
                                                    float* __restrict__ WT, int N) {
    __shared__ float t[32][33];
    const int tx = threadIdx.x & 31, ty = threadIdx.x >> 5;
    const int bn = blockIdx.x * 32, bk = blockIdx.y * 32;
#pragma unroll
    for (int i = 0; i < 32; i += 8)
        t[ty + i][tx] = W[(size_t)(bk + ty + i) * N + bn + tx];
    __syncthreads();
#pragma unroll
    for (int i = 0; i < 32; i += 8)
        WT[(size_t)(bn + ty + i) * 512 + bk + tx] = tf32r(t[tx][ty + i]);
}

// ---------------------------------------------------------------------------
// tf32 mma.sync GEMM (unchanged from R6): C = A[M,512] @ BT[N,512]^T (+bias)
// ---------------------------------------------------------------------------
#define AS_STRIDE 36
#define TILE_F (128 * AS_STRIDE)
#define TILE_B (TILE_F * 4)
#define G_SMEM_BYTES (4 * TILE_B)

__global__ __launch_bounds__(256) void gemm_tf32_mma(
    const float* __restrict__ A, const float* __restrict__ BT,
    float* __restrict__ C, const float* __restrict__ bias, int M, int Nn)
{
    extern __shared__ float smf[];
    const uint32_t sb = smem_u32(smf);
    const int tid = threadIdx.x;
    const int lane = tid & 31;
    const int wid = tid >> 5;
    const int warpM = wid & 1;
    const int warpN = wid >> 1;
    const int m0 = blockIdx.y * 128;
    const int n0 = blockIdx.x * 128;

    const int s_row = tid >> 3;
    const int s_kg = tid & 7;

    float acc[4][4][4];
#pragma unroll
    for (int mt = 0; mt < 4; mt++)
#pragma unroll
        for (int nt = 0; nt < 4; nt++)
#pragma unroll
            for (int r = 0; r < 4; r++) acc[mt][nt][r] = 0.f;

    const int aRow = warpM * 64 + (lane & 7) + ((lane >> 3) & 1) * 8;
    const uint32_t aLane = (uint32_t)(aRow * AS_STRIDE + (lane >> 4) * 4) * 4;
    const int bRow = warpN * 32 + ((lane >> 4) & 1) * 8 + (lane & 7);
    const uint32_t bLane = (uint32_t)(bRow * AS_STRIDE + ((lane >> 3) & 1) * 4) * 4;

    {
#pragma unroll
        for (int i = 0; i < 4; i++) {
            int row = s_row + i * 32;
            uint32_t sa = sb + (uint32_t)(row * AS_STRIDE + s_kg * 4) * 4;
            int szA = (m0 + row < M) ? 16 : 0;
            CP_ASYNC16(sa, &A[(size_t)(m0 + row) * 512 + s_kg * 4], szA);
            uint32_t sbp = sb + 2u * TILE_B + (uint32_t)(row * AS_STRIDE + s_kg * 4) * 4;
            CP_ASYNC16(sbp, &BT[(size_t)(n0 + row) * 512 + s_kg * 4], 16);
        }
        CP_COMMIT();
    }

    for (int c = 0; c < 16; c++) {
        const int b = c & 1;
        CP_WAIT0();
        __syncthreads();

        if (c + 1 < 16) {
            const int nb = b ^ 1;
            const int k0 = (c + 1) * 32;
#pragma unroll
            for (int i = 0; i < 4; i++) {
                int row = s_row + i * 32;
                uint32_t sa = sb + (uint32_t)nb * TILE_B +
                              (uint32_t)(row * AS_STRIDE + s_kg * 4) * 4;
                int szA = (m0 + row < M) ? 16 : 0;
                CP_ASYNC16(sa, &A[(size_t)(m0 + row) * 512 + k0 + s_kg * 4], szA);
                uint32_t sbp = sb + (uint32_t)(2 + nb) * TILE_B +
                               (uint32_t)(row * AS_STRIDE + s_kg * 4) * 4;
                CP_ASYNC16(sbp, &BT[(size_t)(n0 + row) * 512 + k0 + s_kg * 4], 16);
            }
            CP_COMMIT();
        }

        const uint32_t aBuf = sb + (uint32_t)b * TILE_B;
        const uint32_t bBuf = sb + (uint32_t)(2 + b) * TILE_B;
#pragma unroll
        for (int s = 0; s < 4; s++) {
            uint32_t af[4][4];
#pragma unroll
            for (int mt = 0; mt < 4; mt++)
                LDSM_X4(af[mt], aBuf + aLane + (uint32_t)(mt * 16 * AS_STRIDE * 4 + s * 32));
            uint32_t bf[2][4];
#pragma unroll
            for (int p = 0; p < 2; p++)
                LDSM_X4(bf[p], bBuf + bLane + (uint32_t)(p * 16 * AS_STRIDE * 4 + s * 32));
#pragma unroll
            for (int mt = 0; mt < 4; mt++)
#pragma unroll
                for (int nt = 0; nt < 4; nt++)
                    MMA_TF32(acc[mt][nt], af[mt], bf[nt >> 1][(nt & 1) * 2],
                             bf[nt >> 1][(nt & 1) * 2 + 1]);
        }
    }

#pragma unroll
    for (int mt = 0; mt < 4; mt++) {
        const int r0 = m0 + warpM * 64 + mt * 16 + (lane >> 2);
#pragma unroll
        for (int nt = 0; nt < 4; nt++) {
            const int col = n0 + warpN * 32 + nt * 8 + (lane & 3) * 2;
            float bx = 0.f, by = 0.f;
            if (bias) { bx = __ldg(&bias[col]); by = __ldg(&bias[col + 1]); }
            if (r0 < M) {
                float2 v = make_float2(acc[mt][nt][0] + bx, acc[mt][nt][1] + by);
                *(float2*)&C[(size_t)r0 * Nn + col] = v;
            }
            if (r0 + 8 < M) {
                float2 v = make_float2(acc[mt][nt][2] + bx, acc[mt][nt][3] + by);
                *(float2*)&C[(size_t)(r0 + 8) * Nn + col] = v;
            }
        }
    }
}

// ---------------------------------------------------------------------------
// Frame attention v2: tf32 mma.sync flash-style. One CTA per (b,h,f).
// K (197x64) and V^T (64x200) resident; queries in tiles of 32 (2 m-tiles).
// sim: 8 warps = 2 mt x 4 ng over 25 n-tiles (j, padded to 200).
// PV:  8 warps = 2 mt x 4 ng over 8 n-tiles (d), 25 k-steps over j.
// Q and P are hi/lo split (2 MMAs) to cancel A-side tf32 rounding error.
// ---------------------------------------------------------------------------
#define KP2 68    // K/Q smem stride (floats) — ldmatrix conflict-free
#define SSP 204   // S / Vt smem stride (floats) — ldmatrix conflict-free
#define QT2 32

// smem layout (floats)
#define O_K   0                       // 200 x 68  (rows 197..199 zero)
#define O_VT  (O_K + 200 * KP2)       // 64 x 204  (cols 197..199 zero)
#define O_QH  (O_VT + 64 * SSP)       // 32 x 68
#define O_QL  (O_QH + 32 * KP2)       // 32 x 68
#define O_SH  (O_QL + 32 * KP2)       // 32 x 204
#define O_SL  (O_SH + 32 * SSP)       // 32 x 204
#define FA2_FLOATS (O_SL + 32 * SSP)
#define FA2_SMEM (FA2_FLOATS * 4)

__global__ __launch_bounds__(256) void frame_attn_mma(
    const float* __restrict__ qkv, float* __restrict__ attn_out)
{
    extern __shared__ float sm[];
    const uint32_t sb = smem_u32(sm);
    float* Ks = sm + O_K;
    float* Vt = sm + O_VT;
    float* Qh = sm + O_QH;
    float* Ql = sm + O_QL;
    float* Sh = sm + O_SH;
    float* Sl = sm + O_SL;

    const int tid = threadIdx.x;
    const int w = tid >> 5;
    const int l = tid & 31;
    const int bhf = blockIdx.x;
    const int fi = bhf % FF;
    const int bh = bhf / FF;
    const int h = bh % HH;
    const int b = bh / HH;

    const size_t base = (size_t)b * N_TOT * QKV_W;
    const int qoff = h * DHH;
    const int koff = DIMM + h * DHH;
    const int voff = 2 * DIMM + h * DHH;
    const float scale = 0.125f;

    // --- stage K (rounded) and V^T (rounded, transposed) ---
    for (int idx = tid; idx < 197 * 16; idx += 256) {
        int j = idx >> 4, dg = idx & 15;
        int n = (j == 0) ? 0 : (1 + fi * NP + (j - 1));
        const float* src = qkv + base + (size_t)n * QKV_W;
        float4 kv = *(const float4*)&src[koff + dg * 4];
        kv.x = tf32r(kv.x); kv.y = tf32r(kv.y); kv.z = tf32r(kv.z); kv.w = tf32r(kv.w);
        *(float4*)&Ks[j * KP2 + dg * 4] = kv;
        float4 vv = *(const float4*)&src[voff + dg * 4];
        Vt[(dg * 4 + 0) * SSP + j] = tf32r(vv.x);
        Vt[(dg * 4 + 1) * SSP + j] = tf32r(vv.y);
        Vt[(dg * 4 + 2) * SSP + j] = tf32r(vv.z);
        Vt[(dg * 4 + 3) * SSP + j] = tf32r(vv.w);
    }
    // zero pads: K rows 197..199, Vt cols 197..199
    for (int i = tid; i < 3 * KP2; i += 256) Ks[(197 + i / KP2) * KP2 + (i % KP2)] = 0.f;
    for (int i = tid; i < 64 * 3; i += 256) Vt[(i / 3) * SSP + 197 + (i % 3)] = 0.f;
    __syncthreads();

    const int mt = w & 1;
    const int ng = w >> 1;

    for (int qt = 0; qt < NP; qt += QT2) {
        const int qcnt = min(QT2, NP - qt);
        const int active = (qcnt + 15) >> 4;  // 2 or 1 m-tiles

        // --- load Q tile (scaled, hi/lo split); pad rows zeroed ---
        for (int idx = tid; idx < QT2 * 16; idx += 256) {
            int qi = idx >> 4, dg = idx & 15;
            float4 v = make_float4(0.f, 0.f, 0.f, 0.f);
            if (qi < qcnt) {
                int n = 1 + fi * NP + qt + qi;
                v = *(const float4*)&qkv[base + (size_t)n * QKV_W + qoff + dg * 4];
                v.x *= scale; v.y *= scale; v.z *= scale; v.w *= scale;
            }
            float4 hv, lv;
            hv.x = tf32r(v.x); lv.x = tf32r(v.x - hv.x);
            hv.y = tf32r(v.y); lv.y = tf32r(v.y - hv.y);
            hv.z = tf32r(v.z); lv.z = tf32r(v.z - hv.z);
            hv.w = tf32r(v.w); lv.w = tf32r(v.w - hv.w);
            *(float4*)&Qh[qi * KP2 + dg * 4] = hv;
            *(float4*)&Ql[qi * KP2 + dg * 4] = lv;
        }
        __syncthreads();

        // --- sim = Q @ K^T (hi/lo split on Q) ---
        if (mt < active) {
            float sacc[4][2][4];
#pragma unroll
            for (int i = 0; i < 4; i++)
#pragma unroll
                for (int t = 0; t < 2; t++)
#pragma unroll
                    for (int r = 0; r < 4; r++) sacc[i][t][r] = 0.f;

            const uint32_t aoff =
                (uint32_t)((mt * 16 + (l & 7) + ((l >> 3) & 1) * 8) * KP2 + (l >> 4) * 4) * 4;
            const uint32_t aH = sb + O_QH * 4 + aoff;
            const uint32_t aL = sb + O_QL * 4 + aoff;
            const uint32_t brow = (uint32_t)((l & 7) + ((l >> 4) & 1) * 8);
            const uint32_t bcol = (uint32_t)((l >> 3) & 1) * 16;

            for (int s = 0; s < 8; s++) {
                uint32_t ah[4], al[4];
                LDSM_X4(ah, aH + s * 32);
                LDSM_X4(al, aL + s * 32);
#pragma unroll
                for (int i = 0; i < 3; i++) {
                    int p = ng + 4 * i;
                    uint32_t bk[4];
                    LDSM_X4(bk, sb + O_K * 4 +
                                (uint32_t)((16 * p + brow) * KP2) * 4 + bcol + s * 32);
                    MMA_TF32(sacc[i][0], ah, bk[0], bk[1]);
                    MMA_TF32(sacc[i][0], al, bk[0], bk[1]);
                    MMA_TF32(sacc[i][1], ah, bk[2], bk[3]);
                    MMA_TF32(sacc[i][1], al, bk[2], bk[3]);
                }
                if (ng == 0) {  // n-tile 24 (cols 192..199)
                    uint32_t b2[2];
                    LDSM_X2(b2, sb + O_K * 4 +
                                (uint32_t)((192 + (l & 7)) * KP2) * 4 +
                                ((uint32_t)((l >> 3) & 1) * 16) + s * 32);
                    MMA_TF32(sacc[3][0], ah, b2[0], b2[1]);
                    MMA_TF32(sacc[3][0], al, b2[0], b2[1]);
                }
            }
            // write raw logits to Sh
            const int r = mt * 16 + (l >> 2);
#pragma unroll
            for (int i = 0; i < 3; i++) {
                int p = ng + 4 * i;
#pragma unroll
                for (int t = 0; t < 2; t++) {
                    int col = 16 * p + 8 * t + 2 * (l & 3);
                    Sh[r * SSP + col] = sacc[i][t][0];
                    Sh[r * SSP + col + 1] = sacc[i][t][1];
                    Sh[(r + 8) * SSP + col] = sacc[i][t][2];
                    Sh[(r + 8) * SSP + col + 1] = sacc[i][t][3];
                }
            }
            if (ng == 0) {
                int col = 192 + 2 * (l & 3);
                Sh[r * SSP + col] = sacc[3][0][0];
                Sh[r * SSP + col + 1] = sacc[3][0][1];
                Sh[(r + 8) * SSP + col] = sacc[3][0][2];
                Sh[(r + 8) * SSP + col + 1] = sacc[3][0][3];
            }
        }
        __syncthreads();

        // --- softmax (warp w: rows w, w+8, w+16, w+24) + hi/lo split of P ---
#pragma unroll
        for (int t = 0; t < 4; t++) {
            int r = w + 8 * t;
            if (r < qcnt) {
                float* row = Sh + r * SSP;
                float* rl = Sl + r * SSP;
                float m = -1e30f;
                for (int j = l; j < 197; j += 32) m = fmaxf(m, row[j]);
#pragma unroll
                for (int o = 16; o > 0; o >>= 1)
                    m = fmaxf(m, __shfl_xor_sync(0xffffffffu, m, o));
                float ssum = 0.f;
                for (int j = l; j < 197; j += 32) {
                    float e = __expf(row[j] - m);
                    row[j] = e;
                    ssum += e;
                }
#pragma unroll
                for (int o = 16; o > 0; o >>= 1)
                    ssum += __shfl_xor_sync(0xffffffffu, ssum, o);
                float inv = 1.f / ssum;
                for (int j = l; j < 197; j += 32) {
                    float p = row[j] * inv;
                    float ph = tf32r(p);
                    row[j] = ph;
                    rl[j] = tf32r(p - ph);
                }
                if (l < 3) { row[197 + l] = 0.f; rl[197 + l] = 0.f; }
            } else if (r < active * 16) {
                float* row = Sh + r * SSP;
                float* rl = Sl + r * SSP;
                for (int j = l; j < 200; j += 32) { row[j] = 0.f; rl[j] = 0.f; }
            }
        }
        __syncthreads();

        // --- PV = P @ V^T (hi/lo split on P); warp = (mt, 2 d-n-tiles) ---
        if (mt < active) {
            float oacc[2][4];
#pragma unroll
            for (int t = 0; t < 2; t++)
#pragma unroll
                for (int r = 0; r < 4; r++) oacc[t][r] = 0.f;

            const uint32_t aoff =
                (uint32_t)((mt * 16 + (l & 7) + ((l >> 3) & 1) * 8) * SSP + (l >> 4) * 4) * 4;
            const uint32_t aH = sb + O_SH * 4 + aoff;
            const uint32_t aL = sb + O_SL * 4 + aoff;
            const uint32_t bvo = sb + O_VT * 4 +
                (uint32_t)((16 * ng + (l & 7) + ((l >> 4) & 1) * 8) * SSP) * 4 +
                ((uint32_t)((l >> 3) & 1) * 16);

            for (int ks = 0; ks < 25; ks++) {
                uint32_t ah[4], al[4], bv[4];
                LDSM_X4(ah, aH + ks * 32);
                LDSM_X4(al, aL + ks * 32);
                LDSM_X4(bv, bvo + ks * 32);
                MMA_TF32(oacc[0], ah, bv[0], bv[1]);
                MMA_TF32(oacc[0], al, bv[0], bv[1]);
                MMA_TF32(oacc[1], ah, bv[2], bv[3]);
                MMA_TF32(oacc[1], al, bv[2], bv[3]);
            }

            const int rl0 = mt * 16 + (l >> 2);
#pragma unroll
            for (int t = 0; t < 2; t++) {
                int col = h * DHH + ng * 16 + t * 8 + 2 * (l & 3);
                if (rl0 < qcnt) {
                    int n = 1 + fi * NP + qt + rl0;
                    float2 v = make_float2(tf32r(oacc[t][0]), tf32r(oacc[t][1]));
                    *(float2*)&attn_out[((size_t)(b * N_TOT + n)) * DIMM + col] = v;
                }
                if (rl0 + 8 < qcnt) {
                    int n = 1 + fi * NP + qt + rl0 + 8;
                    float2 v = make_float2(tf32r(oacc[t][2]), tf32r(oacc[t][3]));
                    *(float2*)&attn_out[((size_t)(b * N_TOT + n)) * DIMM + col] = v;
                }
            }
        }
        __syncthreads();
    }
}

// ---------------------------------------------------------------------------
// CLS attention (unchanged)
// ---------------------------------------------------------------------------
__global__ __launch_bounds__(256) void cls_attn_kernel(
    const float* __restrict__ qkv, float* __restrict__ attn_out)
{
    __shared__ float q0[64];
    __shared__ float sim[N_TOT];
    __shared__ float red[256];
    __shared__ float acc4[4 * 64];

    const int tid = threadIdx.x;
    const int bh = blockIdx.x;
    const int h = bh % HH;
    const int b = bh / HH;
    const size_t base = (size_t)b * N_TOT * QKV_W;

    if (tid < 64) q0[tid] = qkv[base + h * DHH + tid] * 0.125f;
    __syncthreads();

    for (int n = tid; n < N_TOT; n += 256) {
        const float* kp = qkv + base + (size_t)n * QKV_W + DIMM + h * DHH;
        float dot = 0.f;
#pragma unroll
        for (int d = 0; d < 64; d++) dot += q0[d] * kp[d];
        sim[n] = dot;
    }
    __syncthreads();

    float m = -1e30f;
    for (int n = tid; n < N_TOT; n += 256) m = fmaxf(m, sim[n]);
    red[tid] = m;
    __syncthreads();
    for (int s = 128; s > 0; s >>= 1) {
        if (tid < s) red[tid] = fmaxf(red[tid], red[tid + s]);
        __syncthreads();
    }
    m = red[0];
    __syncthreads();

    float ssum = 0.f;
    for (int n = tid; n < N_TOT; n += 256) {
        float e = __expf(sim[n] - m);
        sim[n] = e;
        ssum += e;
    }
    red[tid] = ssum;
    __syncthreads();
    for (int s = 128; s > 0; s >>= 1) {
        if (tid < s) red[tid] += red[tid + s];
        __syncthreads();
    }
    const float inv = 1.f / red[0];
    __syncthreads();

    const int nn = tid >> 6;
    const int d = tid & 63;
    float a = 0.f;
    for (int n = nn; n < N_TOT; n += 4)
        a += sim[n] * qkv[base + (size_t)n * QKV_W + 2 * DIMM + h * DHH + d];
    acc4[tid] = a;
    __syncthreads();

    if (tid < 64) {
        float v = (acc4[tid] + acc4[tid + 64] + acc4[tid + 128] + acc4[tid + 192]) * inv;
        attn_out[((size_t)b * N_TOT) * DIMM + h * DHH + tid] = tf32r(v);
    }
}

// ---------------------------------------------------------------------------
// Launch
// ---------------------------------------------------------------------------
extern "C" void kernel_launch(void* const* d_in, const int* in_sizes, int n_in,
                              void* d_out, int out_size)
{
    const float* x     = (const float*)d_in[0];
    const float* W_qkv = (const float*)d_in[1];
    const float* W_out = (const float*)d_in[2];
    const float* b_out = (const float*)d_in[3];
    float* out = (float*)d_out;

    void *pq = nullptr, *pa = nullptr, *pw = nullptr, *px = nullptr;
    cudaGetSymbolAddress(&pq, g_qkv);
    cudaGetSymbolAddress(&pa, g_attn);
    cudaGetSymbolAddress(&pw, g_wt);
    cudaGetSymbolAddress(&px, g_xr);
    float* qkv  = (float*)pq;
    float* attn = (float*)pa;
    float* xr   = (float*)px;
    float* wt_qkv = (float*)pw;
    float* wt_out = wt_qkv + (size_t)QKV_W * DIMM;

    cudaFuncSetAttribute(gemm_tf32_mma, cudaFuncAttributeMaxDynamicSharedMemorySize,
                         G_SMEM_BYTES);
    cudaFuncSetAttribute(frame_attn_mma, cudaFuncAttributeMaxDynamicSharedMemorySize,
                         FA2_SMEM);

    // 0) round x; transpose + round weights
    {
        int n4 = BN_TOT * DIMM / 4;
        round_tf32_kernel<<<(n4 + 255) / 256, 256>>>(x, xr, n4);
        transpose512<<<dim3(QKV_W / 32, DIMM / 32), 256>>>(W_qkv, wt_qkv, QKV_W);
        transpose512<<<dim3(DIMM / 32, DIMM / 32), 256>>>(W_out, wt_out, DIMM);
    }

    // 1) QKV GEMM
    {
        dim3 grid(QKV_W / 128, (BN_TOT + 127) / 128);
        gemm_tf32_mma<<<grid, 256, G_SMEM_BYTES>>>(xr, wt_qkv, qkv, nullptr, BN_TOT, QKV_W);
    }

    // 2) Attention
    {
        frame_attn_mma<<<BB * HH * FF, 256, FA2_SMEM>>>(qkv, attn);
        cls_attn_kernel<<<BB * HH, 256>>>(qkv, attn);
    }

    // 3) Output GEMM + bias
    {
        dim3 grid(DIMM / 128, (BN_TOT + 127) / 128);
        gemm_tf32_mma<<<grid, 256, G_SMEM_BYTES>>>(attn, wt_out, out, b_out, BN_TOT, DIMM);
    }
}